// round 1
// baseline (speedup 1.0000x reference)
#include <cuda_runtime.h>
#include <math.h>

#define BB   64
#define TT   1024
#define NDIM 1024
#define MTOT (BB*TT)

// Scratch (allocation-free rule: __device__ globals)
__device__ float g_dec_fea[BB*NDIM];
__device__ float g_scores[MTOT];

// ---------------------------------------------------------------------------
// K0: dec_fea[b,m] = sum_n s_t_hat[b,n] * dec_W[m,n] + dec_b[m]
// grid: 128 blocks x 256 threads; one warp per m, loop over b.
// dec_W row held in registers (read once); s_t_hat (256 KB) stays L2-hot.
// ---------------------------------------------------------------------------
__global__ void dec_fea_kernel(const float* __restrict__ s_t_hat,
                               const float* __restrict__ dec_W,
                               const float* __restrict__ dec_b) {
    const int warp = threadIdx.x >> 5;
    const int lane = threadIdx.x & 31;
    const int m = blockIdx.x * 8 + warp;

    const float* wr = dec_W + (size_t)m * NDIM + lane;
    float w[32];
#pragma unroll
    for (int j = 0; j < 32; ++j) w[j] = wr[j * 32];
    const float bias = dec_b[m];

    for (int b = 0; b < BB; ++b) {
        const float* s = s_t_hat + (size_t)b * NDIM + lane;
        float acc = 0.f;
#pragma unroll
        for (int j = 0; j < 32; ++j) acc += w[j] * s[j * 32];
#pragma unroll
        for (int off = 16; off; off >>= 1)
            acc += __shfl_down_sync(0xffffffffu, acc, off);
        if (lane == 0) g_dec_fea[b * NDIM + m] = acc + bias;
    }
}

// ---------------------------------------------------------------------------
// K1: fused GEMM + tanh·v epilogue.
// scores[row] = sum_m v[m] * tanh( h[row]·W_h[m] + dec_fea[b,m] + cov[row]*W_c[m] )
// Block: 128 rows, loops over all 8 column chunks of 128 (no atomics, fully
// deterministic). 256 threads, 8x8 microtile, TK=16 smem staging (transposed).
// ---------------------------------------------------------------------------
__global__ __launch_bounds__(256, 2)
void score_kernel(const float* __restrict__ h, const float* __restrict__ W_h,
                  const float* __restrict__ W_c, const float* __restrict__ v,
                  const float* __restrict__ coverage) {
    __shared__ float As[16][128];
    __shared__ float Bs[16][128];
    __shared__ float red[128][17];
    __shared__ float score_acc[128];
    __shared__ float dec_s[128], wc_s[128], v_s[128];

    const int tid  = threadIdx.x;
    const int tx   = tid & 15;   // column group (8 cols each)
    const int ty   = tid >> 4;   // row group (8 rows each)
    const int row0 = blockIdx.x * 128;
    const int b    = row0 / TT;  // tiles never straddle a batch boundary

    if (tid < 128) score_acc[tid] = 0.f;

    float cov[8];
#pragma unroll
    for (int i = 0; i < 8; ++i) cov[i] = coverage[row0 + ty * 8 + i];

    for (int nc = 0; nc < NDIM / 128; ++nc) {
        const int m0 = nc * 128;
        if (tid < 128) {
            dec_s[tid] = g_dec_fea[b * NDIM + m0 + tid];
            wc_s[tid]  = W_c[m0 + tid];
            v_s[tid]   = v[m0 + tid];
        }

        float acc[8][8];
#pragma unroll
        for (int i = 0; i < 8; ++i)
#pragma unroll
            for (int j = 0; j < 8; ++j) acc[i][j] = 0.f;

        for (int k0 = 0; k0 < NDIM; k0 += 16) {
            // 128x16 tiles of A (h rows) and B (W_h rows), both K-contiguous.
            int f = tid;
#pragma unroll
            for (int it = 0; it < 2; ++it, f += 256) {
                const int r  = f >> 2;
                const int kq = (f & 3) << 2;
                float4 va = *(const float4*)(h   + (size_t)(row0 + r) * NDIM + k0 + kq);
                As[kq + 0][r] = va.x; As[kq + 1][r] = va.y;
                As[kq + 2][r] = va.z; As[kq + 3][r] = va.w;
                float4 vb = *(const float4*)(W_h + (size_t)(m0  + r) * NDIM + k0 + kq);
                Bs[kq + 0][r] = vb.x; Bs[kq + 1][r] = vb.y;
                Bs[kq + 2][r] = vb.z; Bs[kq + 3][r] = vb.w;
            }
            __syncthreads();
#pragma unroll
            for (int kk = 0; kk < 16; ++kk) {
                float a[8], bb[8];
#pragma unroll
                for (int i = 0; i < 8; ++i) a[i]  = As[kk][ty * 8 + i];
#pragma unroll
                for (int j = 0; j < 8; ++j) bb[j] = Bs[kk][tx * 8 + j];
#pragma unroll
                for (int i = 0; i < 8; ++i)
#pragma unroll
                    for (int j = 0; j < 8; ++j) acc[i][j] += a[i] * bb[j];
            }
            __syncthreads();
        }

        // Fused epilogue: tanh + dot with v, reduce 128 cols per row.
#pragma unroll
        for (int i = 0; i < 8; ++i) {
            float part = 0.f;
#pragma unroll
            for (int j = 0; j < 8; ++j) {
                const int c = tx * 8 + j;
                const float val = acc[i][j] + dec_s[c] + cov[i] * wc_s[c];
                part += tanhf(val) * v_s[c];
            }
            red[ty * 8 + i][tx] = part;
        }
        __syncthreads();
        if (tid < 128) {
            float s = 0.f;
#pragma unroll
            for (int x = 0; x < 16; ++x) s += red[tid][x];
            score_acc[tid] += s;
        }
        __syncthreads();
    }

    if (tid < 128) g_scores[row0 + tid] = score_acc[tid];
}

// ---------------------------------------------------------------------------
// K2: masked softmax + renorm + coverage update. One block per batch row.
// attn[t] = exp(s[t]-max)*mask[t] / sum_t exp(s-max)*mask   (denoms cancel)
// ---------------------------------------------------------------------------
__global__ void softmax_kernel(const float* __restrict__ mask,
                               const float* __restrict__ coverage,
                               float* __restrict__ attn_out,
                               float* __restrict__ cov_out) {
    const int b   = blockIdx.x;
    const int tid = threadIdx.x;          // 256 threads, 4 elems each
    __shared__ float warp_red[8];
    __shared__ float stat[2];

    const float* sc = g_scores + b * TT;
    float sv[4];
    float lmax = -1e30f;
#pragma unroll
    for (int q = 0; q < 4; ++q) {
        sv[q] = sc[tid + 256 * q];
        lmax = fmaxf(lmax, sv[q]);
    }
#pragma unroll
    for (int off = 16; off; off >>= 1)
        lmax = fmaxf(lmax, __shfl_xor_sync(0xffffffffu, lmax, off));
    if ((tid & 31) == 0) warp_red[tid >> 5] = lmax;
    __syncthreads();
    if (tid == 0) {
        float m = warp_red[0];
#pragma unroll
        for (int i = 1; i < 8; ++i) m = fmaxf(m, warp_red[i]);
        stat[0] = m;
    }
    __syncthreads();
    const float M = stat[0];

    float e[4];
    float lsum = 0.f;
#pragma unroll
    for (int q = 0; q < 4; ++q) {
        e[q] = expf(sv[q] - M) * mask[b * TT + tid + 256 * q];
        lsum += e[q];
    }
#pragma unroll
    for (int off = 16; off; off >>= 1)
        lsum += __shfl_xor_sync(0xffffffffu, lsum, off);
    if ((tid & 31) == 0) warp_red[tid >> 5] = lsum;
    __syncthreads();
    if (tid == 0) {
        float s = 0.f;
#pragma unroll
        for (int i = 0; i < 8; ++i) s += warp_red[i];
        stat[1] = 1.0f / s;
    }
    __syncthreads();
    const float inv = stat[1];

#pragma unroll
    for (int q = 0; q < 4; ++q) {
        const int t = tid + 256 * q;
        const float a = e[q] * inv;
        attn_out[b * TT + t] = a;
        cov_out[b * TT + t]  = coverage[b * TT + t] + a;
    }
}

// ---------------------------------------------------------------------------
// K3: c_t[b,n] = sum_t attn[b,t] * h[b,t,n]. Memory-bound (one pass over h).
// grid (64, 8) x 128 threads; attn row staged in smem, coalesced h reads.
// ---------------------------------------------------------------------------
__global__ void ct_kernel(const float* __restrict__ h,
                          const float* __restrict__ attn,
                          float* __restrict__ c_t) {
    const int b = blockIdx.x;
    const int n = blockIdx.y * 128 + threadIdx.x;
    __shared__ float a_s[TT];
    for (int i = threadIdx.x; i < TT; i += 128) a_s[i] = attn[b * TT + i];
    __syncthreads();

    const float* hb = h + (size_t)b * TT * NDIM + n;
    float acc0 = 0.f, acc1 = 0.f, acc2 = 0.f, acc3 = 0.f;
#pragma unroll 4
    for (int t = 0; t < TT; t += 4) {
        acc0 += a_s[t + 0] * hb[(size_t)(t + 0) * NDIM];
        acc1 += a_s[t + 1] * hb[(size_t)(t + 1) * NDIM];
        acc2 += a_s[t + 2] * hb[(size_t)(t + 2) * NDIM];
        acc3 += a_s[t + 3] * hb[(size_t)(t + 3) * NDIM];
    }
    c_t[b * NDIM + n] = (acc0 + acc1) + (acc2 + acc3);
}

// ---------------------------------------------------------------------------
extern "C" void kernel_launch(void* const* d_in, const int* in_sizes, int n_in,
                              void* d_out, int out_size) {
    const float* s_t_hat  = (const float*)d_in[0];
    const float* h        = (const float*)d_in[1];
    const float* mask     = (const float*)d_in[2];
    const float* coverage = (const float*)d_in[3];
    const float* W_h      = (const float*)d_in[4];
    const float* W_c      = (const float*)d_in[5];
    const float* dec_W    = (const float*)d_in[6];
    const float* dec_b    = (const float*)d_in[7];
    const float* v        = (const float*)d_in[8];

    float* out  = (float*)d_out;
    float* c_t  = out;                       // [B, N]
    float* attn = out + (size_t)BB * NDIM;   // [B, T]
    float* covn = attn + (size_t)BB * TT;    // [B, T]

    dec_fea_kernel<<<NDIM / 8, 256>>>(s_t_hat, dec_W, dec_b);
    score_kernel<<<MTOT / 128, 256>>>(h, W_h, W_c, v, coverage);
    softmax_kernel<<<BB, 256>>>(mask, coverage, attn, covn);
    ct_kernel<<<dim3(BB, NDIM / 128), 128>>>(h, attn, c_t);
}